// round 14
// baseline (speedup 1.0000x reference)
#include <cuda_runtime.h>
#include <cuda_fp16.h>
#include <math.h>
#include <stdint.h>

// ---------------------------------------------------------------------------
// TransformerBlock B=8 S=1024 D=1024 H=16 DH=64 F=4096 (fp32 in/out)
// All matmuls: plain fp16 mma.sync.m16n8k16, fp32 accumulate.
// GEMM: BM=128 BN=128 BK=64, 3-stage cp.async (wait_group 1), 2 CTAs/SM.
// ---------------------------------------------------------------------------

#define Bb 8
#define Ss 1024
#define Dd 1024
#define Hh 16
#define DH 64
#define Ff 4096
#define TT (Bb*Ss)

typedef __half fp16;

// ------------------------- static device scratch ---------------------------
__device__ float g_sa[TT*Dd];
__device__ float g_h [TT*Dd];
__device__ float g_f2[TT*Dd];
__device__ float g_mf[Bb*Ss];

__device__ fp16 g_xh [TT*Dd];
__device__ fp16 g_qh [TT*Dd];
__device__ fp16 g_kh [TT*Dd];
__device__ fp16 g_vh [TT*Dd];
__device__ fp16 g_cxh[TT*Dd];
__device__ fp16 g_hh [TT*Dd];
__device__ fp16 g_fh [TT*Ff];
__device__ fp16 g_wqh[Dd*Dd];
__device__ fp16 g_wkh[Dd*Dd];
__device__ fp16 g_wvh[Dd*Dd];
__device__ fp16 g_woh[Dd*Dd];
__device__ fp16 g_w1h[Ff*Dd];
__device__ fp16 g_w2h[Dd*Ff];

// pointer table for batched weight conversion (hi only)
__device__ const float* g_cvt_src[4];
__device__ fp16*        g_cvt_dh [4];

// ------------------------------ helpers ------------------------------------
__device__ __forceinline__ uint32_t smem_u32(const void* p) {
    uint32_t a;
    asm("{ .reg .u64 t; cvta.to.shared.u64 t, %1; cvt.u32.u64 %0, t; }"
        : "=r"(a) : "l"(p));
    return a;
}
__device__ __forceinline__ void cp16(uint32_t s, const void* g) {
    asm volatile("cp.async.cg.shared.global [%0], [%1], 16;" :: "r"(s), "l"(g));
}
#define CP_COMMIT() asm volatile("cp.async.commit_group;" ::: "memory")
#define CP_WAIT0()  asm volatile("cp.async.wait_group 0;" ::: "memory")
#define CP_WAIT1()  asm volatile("cp.async.wait_group 1;" ::: "memory")

#define SWZ(x)   ((x) ^ (((x) >> 3) & 0x70))   // 128B rows

__device__ __forceinline__ void ldsm4(uint32_t* r, uint32_t a) {
    asm volatile("ldmatrix.sync.aligned.m8n8.x4.shared.b16 {%0,%1,%2,%3}, [%4];"
        : "=r"(r[0]), "=r"(r[1]), "=r"(r[2]), "=r"(r[3]) : "r"(a));
}
__device__ __forceinline__ void ldsm4t(uint32_t* r, uint32_t a) {
    asm volatile("ldmatrix.sync.aligned.m8n8.x4.trans.shared.b16 {%0,%1,%2,%3}, [%4];"
        : "=r"(r[0]), "=r"(r[1]), "=r"(r[2]), "=r"(r[3]) : "r"(a));
}
__device__ __forceinline__ void mma_f16(float* d, const uint32_t* a, const uint32_t* b) {
    asm volatile(
        "mma.sync.aligned.m16n8k16.row.col.f32.f16.f16.f32 "
        "{%0,%1,%2,%3}, {%4,%5,%6,%7}, {%8,%9}, {%0,%1,%2,%3};"
        : "+f"(d[0]), "+f"(d[1]), "+f"(d[2]), "+f"(d[3])
        : "r"(a[0]), "r"(a[1]), "r"(a[2]), "r"(a[3]), "r"(b[0]), "r"(b[1]));
}
__device__ __forceinline__ uint32_t packh(float a, float b) {
    __half2 t = __floats2half2_rn(a, b);
    return reinterpret_cast<uint32_t&>(t);
}
__device__ __forceinline__ float gelu_exact(float v) {
    return 0.5f * v * (1.0f + erff(v * 0.70710678118654752440f));
}

// ----------------------------- GEMM core -----------------------------------
// stage: A 16K | W 16K = 32K; three stages = 96K smem -> 2 CTAs/SM.
#define GSTG 32768
#define GEMM_SMEM (3*GSTG)

#define EPI_RES   1
#define EPI_GELU  2

// BM=128 BN=128 BK=64. 8 warps (2x4), warp tile 64x32.
// 3-stage pipeline, wait_group(1): at iter kt, stage kt is complete, stage
// kt+1 may still be in flight; after the sync we issue kt+2 into the buffer
// freed by kt-1. One commit per iteration (empty at the tail keeps counts
// aligned).
template<typename ACC>
__device__ __forceinline__ void gemm_mainloop(
    uint32_t sb, int tid, int lane, int wr, int wc,
    const fp16* A_h, const fp16* W_h,
    int m0, int n0, int K, ACC& acc)
{
    auto load_stage = [&](int st, int kt) {
        const uint32_t s0 = sb + st * GSTG;
        const int k0 = kt * 64;
#pragma unroll
        for (int t = 0; t < 4; t++) {         // A: 128 rows x 128B
            int idx = t * 256 + tid;
            int row = idx >> 3, c = idx & 7;
            uint32_t off = SWZ((uint32_t)(row * 128 + c * 16));
            size_t go = (size_t)(m0 + row) * K + k0 + c * 8;
            cp16(s0 + off, A_h + go);
        }
#pragma unroll
        for (int t = 0; t < 4; t++) {         // W: 128 rows x 128B
            int idx = t * 256 + tid;
            int row = idx >> 3, c = idx & 7;
            uint32_t off = SWZ((uint32_t)(row * 128 + c * 16));
            size_t go = (size_t)(n0 + row) * K + k0 + c * 8;
            cp16(s0 + 16384 + off, W_h + go);
        }
    };

    const int KT = K >> 6;
    load_stage(0, 0); CP_COMMIT();
    load_stage(1, 1); CP_COMMIT();

    const int lr16 = lane & 15;
    const int alc  = (lane >> 4) * 16;
    const int brow = wc * 32 + (lane & 7) + ((lane >> 4) & 1) * 8;
    const int bcol = ((lane >> 3) & 1) * 16;

    int st = 0, stn = 2;       // st = (kt)%3, stn = (kt+2)%3
    for (int kt = 0; kt < KT; kt++) {
        CP_WAIT1();            // stage kt complete (kt+1 may be in flight)
        __syncthreads();       // visible to all; all warps done stage kt-1
        if (kt + 2 < KT) load_stage(stn, kt + 2);
        CP_COMMIT();           // one group per iter (may be empty)

        const uint32_t sA = sb + st * GSTG;
        const uint32_t sB = sA + 16384;

#pragma unroll
        for (int ks = 0; ks < 4; ks++) {
            uint32_t ah[4][4];
#pragma unroll
            for (int i = 0; i < 4; i++) {
                uint32_t off = SWZ((uint32_t)((wr * 64 + i * 16 + lr16) * 128 + ks * 32 + alc));
                ldsm4(ah[i], sA + off);
            }
#pragma unroll
            for (int p = 0; p < 2; p++) {
                uint32_t boff = SWZ((uint32_t)((brow + p * 16) * 128 + ks * 32 + bcol));
                uint32_t bh[4];
                ldsm4(bh, sB + boff);
#pragma unroll
                for (int a = 0; a < 2; a++) {
#pragma unroll
                    for (int i = 0; i < 4; i++)
                        mma_f16(acc[i][p * 2 + a], ah[i], &bh[2 * a]);
                }
            }
        }
        st  = (st  == 2) ? 0 : st + 1;
        stn = (stn == 2) ? 0 : stn + 1;
    }
}

// fused QKV projection: grid (24, 64); blockIdx.x>>3 selects Q/K/V
__global__ void __launch_bounds__(256, 2) gemm_qkv(
    const fp16* __restrict__ xh,
    const fp16* __restrict__ wqh, const fp16* __restrict__ wkh,
    const fp16* __restrict__ wvh,
    const float* __restrict__ bq, const float* __restrict__ bk,
    const float* __restrict__ bv,
    fp16* __restrict__ qh, fp16* __restrict__ kh, fp16* __restrict__ vh)
{
    extern __shared__ char smem[];
    const uint32_t sb = smem_u32(smem);
    const int tid = threadIdx.x;
    const int lane = tid & 31, wid = tid >> 5;
    const int wr = wid >> 2, wc = wid & 3;
    const int mat = blockIdx.x >> 3;
    const int n0 = (blockIdx.x & 7) * 128;
    const int m0 = blockIdx.y * 128;

    const fp16* W_h = (mat == 0) ? wqh : (mat == 1) ? wkh : wvh;
    const float* bias = (mat == 0) ? bq : (mat == 1) ? bk : bv;
    fp16* Ch = (mat == 0) ? qh : (mat == 1) ? kh : vh;
    const float scale = (mat == 0) ? 0.125f : 1.0f;

    float acc[4][4][4];
#pragma unroll
    for (int i = 0; i < 4; i++)
#pragma unroll
        for (int j = 0; j < 4; j++)
#pragma unroll
            for (int e = 0; e < 4; e++) acc[i][j][e] = 0.f;

    gemm_mainloop(sb, tid, lane, wr, wc, xh, W_h, m0, n0, Dd, acc);

#pragma unroll
    for (int i = 0; i < 4; i++) {
        const int r0 = m0 + wr * 64 + i * 16 + (lane >> 2);
#pragma unroll
        for (int j = 0; j < 4; j++) {
            const int n = n0 + wc * 32 + j * 8 + 2 * (lane & 3);
            const float2 b2 = *(const float2*)&bias[n];
#pragma unroll
            for (int hf = 0; hf < 2; hf++) {
                const int m = r0 + hf * 8;
                float v0 = (acc[i][j][hf * 2 + 0] + b2.x) * scale;
                float v1 = (acc[i][j][hf * 2 + 1] + b2.y) * scale;
                const size_t o = (((size_t)(m >> 10) * Hh + (n >> 6)) * Ss + (m & 1023)) * DH + (n & 63);
                *(uint32_t*)(Ch + o) = packh(v0, v1);
            }
        }
    }
}

template<int EPI>
__global__ void __launch_bounds__(256, 2) gemm_mma(
    const fp16* __restrict__ A_h, const fp16* __restrict__ W_h,
    const float* __restrict__ bias, const float* __restrict__ res,
    float* __restrict__ Cf, fp16* __restrict__ Ch,
    int N, int K)
{
    extern __shared__ char smem[];
    const uint32_t sb = smem_u32(smem);
    const int tid = threadIdx.x;
    const int lane = tid & 31, wid = tid >> 5;
    const int wr = wid >> 2, wc = wid & 3;
    const int m0 = blockIdx.y * 128, n0 = blockIdx.x * 128;

    float acc[4][4][4];
#pragma unroll
    for (int i = 0; i < 4; i++)
#pragma unroll
        for (int j = 0; j < 4; j++)
#pragma unroll
            for (int e = 0; e < 4; e++) acc[i][j][e] = 0.f;

    gemm_mainloop(sb, tid, lane, wr, wc, A_h, W_h, m0, n0, K, acc);

#pragma unroll
    for (int i = 0; i < 4; i++) {
        const int r0 = m0 + wr * 64 + i * 16 + (lane >> 2);
#pragma unroll
        for (int j = 0; j < 4; j++) {
            const int n = n0 + wc * 32 + j * 8 + 2 * (lane & 3);
            const float2 b2 = *(const float2*)&bias[n];
#pragma unroll
            for (int hf = 0; hf < 2; hf++) {
                const int m = r0 + hf * 8;
                float v0 = acc[i][j][hf * 2 + 0] + b2.x;
                float v1 = acc[i][j][hf * 2 + 1] + b2.y;
                if (EPI == EPI_RES) {
                    const size_t o = (size_t)m * N + n;
                    const float2 rr = *(const float2*)&res[o];
                    float2 w; w.x = v0 + rr.x; w.y = v1 + rr.y;
                    *(float2*)&Cf[o] = w;
                } else { // EPI_GELU -> fp16
                    const size_t o = (size_t)m * N + n;
                    *(uint32_t*)(Ch + o) = packh(gelu_exact(v0), gelu_exact(v1));
                }
            }
        }
    }
}

// --------------------------- flash attention (mma) --------------------------
// Q 16K | stage{Kh 16K, Vh 16K} x3 | mask 3x512B; 3-stage, wait_group 1.
#define ATT_Q   0
#define ATT_ST  16384
#define ATT_STG 32768
#define ATT_MSK (ATT_ST + 3*ATT_STG)
#define ATT_SMEM (ATT_MSK + 1536)

__global__ void __launch_bounds__(256) attn_mma(
    const fp16* __restrict__ qh, const fp16* __restrict__ kh,
    const fp16* __restrict__ vh,
    const float* __restrict__ mf,
    fp16* __restrict__ oh)
{
    extern __shared__ char smem[];
    const uint32_t sb = smem_u32(smem);
    const int tid = threadIdx.x;
    const int lane = tid & 31, wid = tid >> 5;
    const int b = blockIdx.z, h = blockIdx.y, q0 = blockIdx.x * 128;

    const size_t bh_off = ((size_t)(b * Hh + h) * Ss) * DH;
    const fp16* qhp = qh + bh_off + (size_t)q0 * DH;
    const fp16* khp = kh + bh_off;
    const fp16* vhp = vh + bh_off;
    const float* mfb = mf + b * Ss;

    auto load_kv = [&](int st, int kt) {
        const uint32_t s0 = sb + ATT_ST + st * ATT_STG;
        const int kv0 = kt * 128;
#pragma unroll
        for (int t = 0; t < 4; t++) {
            int idx = t * 256 + tid;
            int row = idx >> 3, c = idx & 7;
            uint32_t off = SWZ((uint32_t)(row * 128 + c * 16));
            size_t go = (size_t)(kv0 + row) * DH + c * 8;
            cp16(s0 + off,         khp + go);
            cp16(s0 + 16384 + off, vhp + go);
        }
        if (tid < 32) cp16(sb + ATT_MSK + st * 512 + tid * 16, mfb + kv0 + tid * 4);
    };

    {
#pragma unroll
        for (int t = 0; t < 4; t++) {
            int idx = t * 256 + tid;
            int row = idx >> 3, c = idx & 7;
            uint32_t off = SWZ((uint32_t)(row * 128 + c * 16));
            size_t go = (size_t)row * DH + c * 8;
            cp16(sb + ATT_Q + off, qhp + go);
        }
        load_kv(0, 0); CP_COMMIT();
        load_kv(1, 1); CP_COMMIT();
    }

    uint32_t qfh[4][4];
    float oacc[8][4];
#pragma unroll
    for (int q = 0; q < 8; q++)
#pragma unroll
        for (int e = 0; e < 4; e++) oacc[q][e] = 0.f;
    float mrow0 = -INFINITY, mrow1 = -INFINITY, lsum0 = 0.f, lsum1 = 0.f;

    const int lr16 = lane & 15;
    const int alc  = (lane >> 4) * 16;
    const int brow = (lane & 7) + ((lane >> 4) & 1) * 8;
    const int bcol = ((lane >> 3) & 1) * 16;
    const int vrow = (lane & 7) + ((lane >> 3) & 1) * 8;
    const int vcol = (lane >> 4) * 16;

    const int NKV = Ss / 128;
    int st = 0, stn = 2;
    for (int kt = 0; kt < NKV; kt++) {
        CP_WAIT1();            // stage kt (and Q on kt==0) complete
        __syncthreads();
        if (kt + 2 < NKV) load_kv(stn, kt + 2);
        CP_COMMIT();

        if (kt == 0) {
#pragma unroll
            for (int ks = 0; ks < 4; ks++) {
                uint32_t off = SWZ((uint32_t)((wid * 16 + lr16) * 128 + ks * 32 + alc));
                ldsm4(qfh[ks], sb + ATT_Q + off);
            }
        }

        const uint32_t sK = sb + ATT_ST + st * ATT_STG;
        const uint32_t sV = sK + 16384;
        const uint32_t sM = sb + ATT_MSK + st * 512;

        float sacc[16][4];
#pragma unroll
        for (int j = 0; j < 16; j++)
#pragma unroll
            for (int e = 0; e < 4; e++) sacc[j][e] = 0.f;

#pragma unroll
        for (int p = 0; p < 8; p++) {
#pragma unroll
            for (int ks = 0; ks < 4; ks++) {
                uint32_t koff = SWZ((uint32_t)((p * 16 + brow) * 128 + ks * 32 + bcol));
                uint32_t kbh[4];
                ldsm4(kbh, sK + koff);
#pragma unroll
                for (int a = 0; a < 2; a++)
                    mma_f16(sacc[p * 2 + a], qfh[ks], &kbh[2 * a]);
            }
        }

        float mx0 = -INFINITY, mx1 = -INFINITY;
#pragma unroll
        for (int j = 0; j < 16; j++) {
            mx0 = fmaxf(mx0, fmaxf(sacc[j][0], sacc[j][1]));
            mx1 = fmaxf(mx1, fmaxf(sacc[j][2], sacc[j][3]));
        }
        mx0 = fmaxf(mx0, __shfl_xor_sync(0xffffffffu, mx0, 1));
        mx0 = fmaxf(mx0, __shfl_xor_sync(0xffffffffu, mx0, 2));
        mx1 = fmaxf(mx1, __shfl_xor_sync(0xffffffffu, mx1, 1));
        mx1 = fmaxf(mx1, __shfl_xor_sync(0xffffffffu, mx1, 2));
        const float mnew0 = fmaxf(mrow0, mx0);
        const float mnew1 = fmaxf(mrow1, mx1);
        const float al0 = __expf(mrow0 - mnew0);
        const float al1 = __expf(mrow1 - mnew1);
        float ls0 = 0.f, ls1 = 0.f;
#pragma unroll
        for (int j = 0; j < 16; j++) {
            float2 mv;
            asm volatile("ld.shared.v2.f32 {%0,%1}, [%2];"
                : "=f"(mv.x), "=f"(mv.y)
                : "r"(sM + (uint32_t)((j * 8 + 2 * (lane & 3)) * 4)));
            float p0 = __expf(sacc[j][0] - mnew0) * mv.x;
            float p1 = __expf(sacc[j][1] - mnew0) * mv.y;
            float p2 = __expf(sacc[j][2] - mnew1) * mv.x;
            float p3 = __expf(sacc[j][3] - mnew1) * mv.y;
            sacc[j][0] = p0; sacc[j][1] = p1; sacc[j][2] = p2; sacc[j][3] = p3;
            ls0 += p0 + p1; ls1 += p2 + p3;
        }
        ls0 += __shfl_xor_sync(0xffffffffu, ls0, 1);
        ls0 += __shfl_xor_sync(0xffffffffu, ls0, 2);
        ls1 += __shfl_xor_sync(0xffffffffu, ls1, 1);
        ls1 += __shfl_xor_sync(0xffffffffu, ls1, 2);
        lsum0 = lsum0 * al0 + ls0;
        lsum1 = lsum1 * al1 + ls1;
        mrow0 = mnew0; mrow1 = mnew1;
#pragma unroll
        for (int q = 0; q < 8; q++) {
            oacc[q][0] *= al0; oacc[q][1] *= al0;
            oacc[q][2] *= al1; oacc[q][3] *= al1;
        }

#pragma unroll
        for (int ks = 0; ks < 8; ks++) {
            uint32_t ph[4];
            {
                const float* s0 = sacc[2 * ks];
                const float* s1 = sacc[2 * ks + 1];
                ph[0] = packh(s0[0], s0[1]); ph[1] = packh(s0[2], s0[3]);
                ph[2] = packh(s1[0], s1[1]); ph[3] = packh(s1[2], s1[3]);
            }
#pragma unroll
            for (int q = 0; q < 4; q++) {
                uint32_t voff = SWZ((uint32_t)((ks * 16 + vrow) * 128 + q * 32 + vcol));
                uint32_t vbh[4];
                ldsm4t(vbh, sV + voff);
#pragma unroll
                for (int a = 0; a < 2; a++)
                    mma_f16(oacc[q * 2 + a], ph, &vbh[2 * a]);
            }
        }
        st  = (st  == 2) ? 0 : st + 1;
        stn = (stn == 2) ? 0 : stn + 1;
    }

    const float inv0 = 1.f / lsum0;
    const float inv1 = 1.f / lsum1;
    const int tok0 = b * Ss + q0 + wid * 16 + (lane >> 2);
#pragma unroll
    for (int q = 0; q < 8; q++) {
        const int col = h * DH + q * 8 + 2 * (lane & 3);
        *(uint32_t*)(oh + (size_t)tok0 * Dd + col) =
            packh(oacc[q][0] * inv0, oacc[q][1] * inv0);
        *(uint32_t*)(oh + (size_t)(tok0 + 8) * Dd + col) =
            packh(oacc[q][2] * inv1, oacc[q][3] * inv1);
    }
}

// ------------------------------ LayerNorm -----------------------------------
template<bool WB>
__global__ void __launch_bounds__(256) ln_k(
    const float* __restrict__ X, const float* __restrict__ gg,
    const float* __restrict__ bb, float* __restrict__ Y,
    fp16* __restrict__ Yh)
{
    __shared__ float red[16];
    const int row = blockIdx.x, tid = threadIdx.x;
    const float4 x = ((const float4*)(X + (size_t)row * Dd))[tid];
    float s  = x.x + x.y + x.z + x.w;
    float s2 = x.x*x.x + x.y*x.y + x.z*x.z + x.w*x.w;
#pragma unroll
    for (int o = 16; o; o >>= 1) {
        s  += __shfl_xor_sync(0xffffffffu, s,  o);
        s2 += __shfl_xor_sync(0xffffffffu, s2, o);
    }
    const int w = tid >> 5, lane = tid & 31;
    if (lane == 0) { red[w] = s; red[8 + w] = s2; }
    __syncthreads();
    if (tid < 32) {
        float a = (tid < 8) ? red[tid]     : 0.f;
        float c = (tid < 8) ? red[8 + tid] : 0.f;
#pragma unroll
        for (int o = 4; o; o >>= 1) {
            a += __shfl_xor_sync(0xffffffffu, a, o);
            c += __shfl_xor_sync(0xffffffffu, c, o);
        }
        if (tid == 0) { red[0] = a; red[8] = c; }
    }
    __syncthreads();
    const float mean = red[0] * (1.f / Dd);
    const float var  = red[8] * (1.f / Dd) - mean * mean;
    const float rstd = rsqrtf(var + 1e-12f);
    const float4 gv = ((const float4*)gg)[tid];
    const float4 bv = ((const float4*)bb)[tid];
    float4 y;
    y.x = (x.x - mean) * rstd * gv.x + bv.x;
    y.y = (x.y - mean) * rstd * gv.y + bv.y;
    y.z = (x.z - mean) * rstd * gv.z + bv.z;
    y.w = (x.w - mean) * rstd * gv.w + bv.w;
    ((float4*)(Y + (size_t)row * Dd))[tid] = y;
    if (WB) {
        uint2 vh2;
        vh2.x = packh(y.x, y.y);  vh2.y = packh(y.z, y.w);
        ((uint2*)(Yh + (size_t)row * Dd))[tid] = vh2;
    }
}

// -------------------------- fp32 -> fp16 conversions ------------------------
__global__ void __launch_bounds__(256) cvth_k(
    const float* __restrict__ X, fp16* __restrict__ Hc, int n4)
{
    int i = blockIdx.x * 256 + threadIdx.x;
    if (i >= n4) return;
    float4 v = ((const float4*)X)[i];
    uint2 vh2;
    vh2.x = packh(v.x, v.y);  vh2.y = packh(v.z, v.w);
    ((uint2*)Hc)[i] = vh2;
}

__global__ void __launch_bounds__(256) cvt4h_k(int n4)
{
    const int a = blockIdx.y;
    int i = blockIdx.x * 256 + threadIdx.x;
    if (i >= n4) return;
    const float* X = g_cvt_src[a];
    fp16* Hc = g_cvt_dh[a];
    float4 v = ((const float4*)X)[i];
    uint2 vh2;
    vh2.x = packh(v.x, v.y);  vh2.y = packh(v.z, v.w);
    ((uint2*)Hc)[i] = vh2;
}

__global__ void __launch_bounds__(256) maskf_k(const int* __restrict__ m,
                                              float* __restrict__ mfo, int n)
{
    int i = blockIdx.x * 256 + threadIdx.x;
    if (i < n) mfo[i] = (m[i] != 0) ? 1.f : 0.f;
}

// ------------------------------ launch --------------------------------------
extern "C" void kernel_launch(void* const* d_in, const int* in_sizes, int n_in,
                              void* d_out, int out_size)
{
    const float* x    = (const float*)d_in[0];
    const int*   amsk = (const int*)  d_in[1];
    const float* Wq   = (const float*)d_in[2];
    const float* bq   = (const float*)d_in[3];
    const float* Wk   = (const float*)d_in[4];
    const float* bk   = (const float*)d_in[5];
    const float* Wv   = (const float*)d_in[6];
    const float* bv   = (const float*)d_in[7];
    const float* Wo   = (const float*)d_in[8];
    const float* bo   = (const float*)d_in[9];
    const float* ln1g = (const float*)d_in[10];
    const float* ln1b = (const float*)d_in[11];
    const float* W1   = (const float*)d_in[12];
    const float* b1   = (const float*)d_in[13];
    const float* W2   = (const float*)d_in[14];
    const float* b2   = (const float*)d_in[15];
    const float* ln2g = (const float*)d_in[16];
    const float* ln2b = (const float*)d_in[17];
    float* out = (float*)d_out;

    float *sap, *hp, *f2p, *mfp;
    fp16 *xh, *qhp, *khp, *vhp, *cxh, *hhp, *fhp;
    fp16 *wqh, *wkh, *wvh, *woh, *w1h, *w2h;
    cudaGetSymbolAddress((void**)&sap, g_sa);  cudaGetSymbolAddress((void**)&hp,  g_h);
    cudaGetSymbolAddress((void**)&f2p, g_f2);  cudaGetSymbolAddress((void**)&mfp, g_mf);
    cudaGetSymbolAddress((void**)&xh,  g_xh);
    cudaGetSymbolAddress((void**)&qhp, g_qh);
    cudaGetSymbolAddress((void**)&khp, g_kh);  cudaGetSymbolAddress((void**)&vhp, g_vh);
    cudaGetSymbolAddress((void**)&cxh, g_cxh);
    cudaGetSymbolAddress((void**)&hhp, g_hh);
    cudaGetSymbolAddress((void**)&fhp, g_fh);
    cudaGetSymbolAddress((void**)&wqh, g_wqh); cudaGetSymbolAddress((void**)&wkh, g_wkh);
    cudaGetSymbolAddress((void**)&wvh, g_wvh); cudaGetSymbolAddress((void**)&woh, g_woh);
    cudaGetSymbolAddress((void**)&w1h, g_w1h); cudaGetSymbolAddress((void**)&w2h, g_w2h);

    static const float* h_src[4];
    static fp16* h_dh[4];
    h_src[0] = Wq; h_src[1] = Wk; h_src[2] = Wv; h_src[3] = Wo;
    h_dh[0] = wqh; h_dh[1] = wkh; h_dh[2] = wvh; h_dh[3] = woh;
    void *d_src_tab, *d_dh_tab;
    cudaGetSymbolAddress(&d_src_tab, g_cvt_src);
    cudaGetSymbolAddress(&d_dh_tab,  g_cvt_dh);
    cudaMemcpyAsync(d_src_tab, h_src, sizeof(h_src), cudaMemcpyHostToDevice);
    cudaMemcpyAsync(d_dh_tab,  h_dh,  sizeof(h_dh),  cudaMemcpyHostToDevice);

    cudaFuncSetAttribute(gemm_qkv,           cudaFuncAttributeMaxDynamicSharedMemorySize, GEMM_SMEM);
    cudaFuncSetAttribute(gemm_mma<EPI_RES>,  cudaFuncAttributeMaxDynamicSharedMemorySize, GEMM_SMEM);
    cudaFuncSetAttribute(gemm_mma<EPI_GELU>, cudaFuncAttributeMaxDynamicSharedMemorySize, GEMM_SMEM);
    cudaFuncSetAttribute(attn_mma, cudaFuncAttributeMaxDynamicSharedMemorySize, ATT_SMEM);

    dim3 gD(Dd/128, TT/128);    // (8, 64)
    dim3 gF(Ff/128, TT/128);    // (32, 64)

    // Launches: 1 cvt_x, 2 cvt4h(weights), 3 maskf, 4 qkv, 5 attn, 6 O-gemm.
    cvth_k<<<(TT*Dd/4 + 255)/256, 256>>>(x, xh, TT*Dd/4);                       // 1
    cvt4h_k<<<dim3((Dd*Dd/4 + 255)/256, 4), 256>>>(Dd*Dd/4);                    // 2
    maskf_k<<<(Bb*Ss + 255)/256, 256>>>(amsk, mfp, Bb*Ss);                      // 3

    // 4. fused QKV projection
    gemm_qkv<<<dim3(24, TT/128), 256, GEMM_SMEM>>>(xh, wqh, wkh, wvh,
                                                   bq, bk, bv, qhp, khp, vhp);

    // 5. attention -> ctx fp16
    attn_mma<<<dim3(Ss/128, Hh, Bb), 256, ATT_SMEM>>>(qhp, khp, vhp, mfp, cxh);

    // 6. output projection + residual (fp32)
    gemm_mma<EPI_RES><<<gD, 256, GEMM_SMEM>>>(cxh, woh, bo, x,
                                              sap, nullptr, Dd, Dd);

    // 7. LN1 -> fp32 + fp16
    ln_k<true><<<TT, 256>>>(sap, ln1g, ln1b, hp, hhp);

    // 8. cvt W1
    cvth_k<<<(Ff*Dd/4 + 255)/256, 256>>>(W1, w1h, Ff*Dd/4);

    // 9. FFN up + gelu -> fp16
    gemm_mma<EPI_GELU><<<gF, 256, GEMM_SMEM>>>(hhp, w1h, b1, nullptr,
                                               nullptr, fhp, Ff, Dd);

    // 10. cvt W2
    cvth_k<<<(Dd*Ff/4 + 255)/256, 256>>>(W2, w2h, Dd*Ff/4);

    // 11. FFN down + residual (fp32)
    gemm_mma<EPI_RES><<<gD, 256, GEMM_SMEM>>>(fhp, w2h, b2, hp,
                                              f2p, nullptr, Dd, Ff);

    // 12. LN2 -> output
    ln_k<false><<<TT, 256>>>(f2p, ln2g, ln2b, out, nullptr);
}

// round 17
// speedup vs baseline: 1.0109x; 1.0109x over previous
#include <cuda_runtime.h>
#include <cuda_fp16.h>
#include <math.h>
#include <stdint.h>

// ---------------------------------------------------------------------------
// TransformerBlock B=8 S=1024 D=1024 H=16 DH=64 F=4096 (fp32 in/out)
// All matmuls: plain fp16 mma.sync.m16n8k16, fp32 accumulate.
// GEMM: BM=128 BN=128 BK=64, 3-stage cp.async, 2 CTAs/SM.
// Attention: 128 q-rows/CTA, KV tile 64, 3-stage, 2 CTAs/SM.
// ---------------------------------------------------------------------------

#define Bb 8
#define Ss 1024
#define Dd 1024
#define Hh 16
#define DH 64
#define Ff 4096
#define TT (Bb*Ss)

typedef __half fp16;

// ------------------------- static device scratch ---------------------------
__device__ float g_sa[TT*Dd];
__device__ float g_h [TT*Dd];
__device__ float g_f2[TT*Dd];
__device__ float g_mf[Bb*Ss];

__device__ fp16 g_xh [TT*Dd];
__device__ fp16 g_qh [TT*Dd];
__device__ fp16 g_kh [TT*Dd];
__device__ fp16 g_vh [TT*Dd];
__device__ fp16 g_cxh[TT*Dd];
__device__ fp16 g_hh [TT*Dd];
__device__ fp16 g_fh [TT*Ff];
__device__ fp16 g_wqh[Dd*Dd];
__device__ fp16 g_wkh[Dd*Dd];
__device__ fp16 g_wvh[Dd*Dd];
__device__ fp16 g_woh[Dd*Dd];
__device__ fp16 g_w1h[Ff*Dd];
__device__ fp16 g_w2h[Dd*Ff];

// pointer table for batched weight conversion (hi only)
__device__ const float* g_cvt_src[4];
__device__ fp16*        g_cvt_dh [4];

// ------------------------------ helpers ------------------------------------
__device__ __forceinline__ uint32_t smem_u32(const void* p) {
    uint32_t a;
    asm("{ .reg .u64 t; cvta.to.shared.u64 t, %1; cvt.u32.u64 %0, t; }"
        : "=r"(a) : "l"(p));
    return a;
}
__device__ __forceinline__ void cp16(uint32_t s, const void* g) {
    asm volatile("cp.async.cg.shared.global [%0], [%1], 16;" :: "r"(s), "l"(g));
}
#define CP_COMMIT() asm volatile("cp.async.commit_group;" ::: "memory")
#define CP_WAIT0()  asm volatile("cp.async.wait_group 0;" ::: "memory")
#define CP_WAIT1()  asm volatile("cp.async.wait_group 1;" ::: "memory")

#define SWZ(x)   ((x) ^ (((x) >> 3) & 0x70))   // 128B rows

__device__ __forceinline__ void ldsm4(uint32_t* r, uint32_t a) {
    asm volatile("ldmatrix.sync.aligned.m8n8.x4.shared.b16 {%0,%1,%2,%3}, [%4];"
        : "=r"(r[0]), "=r"(r[1]), "=r"(r[2]), "=r"(r[3]) : "r"(a));
}
__device__ __forceinline__ void ldsm4t(uint32_t* r, uint32_t a) {
    asm volatile("ldmatrix.sync.aligned.m8n8.x4.trans.shared.b16 {%0,%1,%2,%3}, [%4];"
        : "=r"(r[0]), "=r"(r[1]), "=r"(r[2]), "=r"(r[3]) : "r"(a));
}
__device__ __forceinline__ void mma_f16(float* d, const uint32_t* a, const uint32_t* b) {
    asm volatile(
        "mma.sync.aligned.m16n8k16.row.col.f32.f16.f16.f32 "
        "{%0,%1,%2,%3}, {%4,%5,%6,%7}, {%8,%9}, {%0,%1,%2,%3};"
        : "+f"(d[0]), "+f"(d[1]), "+f"(d[2]), "+f"(d[3])
        : "r"(a[0]), "r"(a[1]), "r"(a[2]), "r"(a[3]), "r"(b[0]), "r"(b[1]));
}
__device__ __forceinline__ uint32_t packh(float a, float b) {
    __half2 t = __floats2half2_rn(a, b);
    return reinterpret_cast<uint32_t&>(t);
}
__device__ __forceinline__ float gelu_exact(float v) {
    return 0.5f * v * (1.0f + erff(v * 0.70710678118654752440f));
}

// ----------------------------- GEMM core -----------------------------------
// stage: A 16K | W 16K = 32K; three stages = 96K smem -> 2 CTAs/SM.
#define GSTG 32768
#define GEMM_SMEM (3*GSTG)

#define EPI_RES   1
#define EPI_GELU  2

template<typename ACC>
__device__ __forceinline__ void gemm_mainloop(
    uint32_t sb, int tid, int lane, int wr, int wc,
    const fp16* A_h, const fp16* W_h,
    int m0, int n0, int K, ACC& acc)
{
    auto load_stage = [&](int st, int kt) {
        const uint32_t s0 = sb + st * GSTG;
        const int k0 = kt * 64;
#pragma unroll
        for (int t = 0; t < 4; t++) {         // A: 128 rows x 128B
            int idx = t * 256 + tid;
            int row = idx >> 3, c = idx & 7;
            uint32_t off = SWZ((uint32_t)(row * 128 + c * 16));
            size_t go = (size_t)(m0 + row) * K + k0 + c * 8;
            cp16(s0 + off, A_h + go);
        }
#pragma unroll
        for (int t = 0; t < 4; t++) {         // W: 128 rows x 128B
            int idx = t * 256 + tid;
            int row = idx >> 3, c = idx & 7;
            uint32_t off = SWZ((uint32_t)(row * 128 + c * 16));
            size_t go = (size_t)(n0 + row) * K + k0 + c * 8;
            cp16(s0 + 16384 + off, W_h + go);
        }
    };

    const int KT = K >> 6;
    load_stage(0, 0); CP_COMMIT();
    load_stage(1, 1); CP_COMMIT();

    const int lr16 = lane & 15;
    const int alc  = (lane >> 4) * 16;
    const int brow = wc * 32 + (lane & 7) + ((lane >> 4) & 1) * 8;
    const int bcol = ((lane >> 3) & 1) * 16;

    int st = 0, stn = 2;
    for (int kt = 0; kt < KT; kt++) {
        CP_WAIT1();
        __syncthreads();
        if (kt + 2 < KT) load_stage(stn, kt + 2);
        CP_COMMIT();

        const uint32_t sA = sb + st * GSTG;
        const uint32_t sB = sA + 16384;

#pragma unroll
        for (int ks = 0; ks < 4; ks++) {
            uint32_t ah[4][4];
#pragma unroll
            for (int i = 0; i < 4; i++) {
                uint32_t off = SWZ((uint32_t)((wr * 64 + i * 16 + lr16) * 128 + ks * 32 + alc));
                ldsm4(ah[i], sA + off);
            }
#pragma unroll
            for (int p = 0; p < 2; p++) {
                uint32_t boff = SWZ((uint32_t)((brow + p * 16) * 128 + ks * 32 + bcol));
                uint32_t bh[4];
                ldsm4(bh, sB + boff);
#pragma unroll
                for (int a = 0; a < 2; a++) {
#pragma unroll
                    for (int i = 0; i < 4; i++)
                        mma_f16(acc[i][p * 2 + a], ah[i], &bh[2 * a]);
                }
            }
        }
        st  = (st  == 2) ? 0 : st + 1;
        stn = (stn == 2) ? 0 : stn + 1;
    }
}

// fused QKV projection: grid (24, 64); blockIdx.x>>3 selects Q/K/V
__global__ void __launch_bounds__(256, 2) gemm_qkv(
    const fp16* __restrict__ xh,
    const fp16* __restrict__ wqh, const fp16* __restrict__ wkh,
    const fp16* __restrict__ wvh,
    const float* __restrict__ bq, const float* __restrict__ bk,
    const float* __restrict__ bv,
    fp16* __restrict__ qh, fp16* __restrict__ kh, fp16* __restrict__ vh)
{
    extern __shared__ char smem[];
    const uint32_t sb = smem_u32(smem);
    const int tid = threadIdx.x;
    const int lane = tid & 31, wid = tid >> 5;
    const int wr = wid >> 2, wc = wid & 3;
    const int mat = blockIdx.x >> 3;
    const int n0 = (blockIdx.x & 7) * 128;
    const int m0 = blockIdx.y * 128;

    const fp16* W_h = (mat == 0) ? wqh : (mat == 1) ? wkh : wvh;
    const float* bias = (mat == 0) ? bq : (mat == 1) ? bk : bv;
    fp16* Ch = (mat == 0) ? qh : (mat == 1) ? kh : vh;
    const float scale = (mat == 0) ? 0.125f : 1.0f;

    float acc[4][4][4];
#pragma unroll
    for (int i = 0; i < 4; i++)
#pragma unroll
        for (int j = 0; j < 4; j++)
#pragma unroll
            for (int e = 0; e < 4; e++) acc[i][j][e] = 0.f;

    gemm_mainloop(sb, tid, lane, wr, wc, xh, W_h, m0, n0, Dd, acc);

#pragma unroll
    for (int i = 0; i < 4; i++) {
        const int r0 = m0 + wr * 64 + i * 16 + (lane >> 2);
#pragma unroll
        for (int j = 0; j < 4; j++) {
            const int n = n0 + wc * 32 + j * 8 + 2 * (lane & 3);
            const float2 b2 = *(const float2*)&bias[n];
#pragma unroll
            for (int hf = 0; hf < 2; hf++) {
                const int m = r0 + hf * 8;
                float v0 = (acc[i][j][hf * 2 + 0] + b2.x) * scale;
                float v1 = (acc[i][j][hf * 2 + 1] + b2.y) * scale;
                const size_t o = (((size_t)(m >> 10) * Hh + (n >> 6)) * Ss + (m & 1023)) * DH + (n & 63);
                *(uint32_t*)(Ch + o) = packh(v0, v1);
            }
        }
    }
}

template<int EPI>
__global__ void __launch_bounds__(256, 2) gemm_mma(
    const fp16* __restrict__ A_h, const fp16* __restrict__ W_h,
    const float* __restrict__ bias, const float* __restrict__ res,
    float* __restrict__ Cf, fp16* __restrict__ Ch,
    int N, int K)
{
    extern __shared__ char smem[];
    const uint32_t sb = smem_u32(smem);
    const int tid = threadIdx.x;
    const int lane = tid & 31, wid = tid >> 5;
    const int wr = wid >> 2, wc = wid & 3;
    const int m0 = blockIdx.y * 128, n0 = blockIdx.x * 128;

    float acc[4][4][4];
#pragma unroll
    for (int i = 0; i < 4; i++)
#pragma unroll
        for (int j = 0; j < 4; j++)
#pragma unroll
            for (int e = 0; e < 4; e++) acc[i][j][e] = 0.f;

    gemm_mainloop(sb, tid, lane, wr, wc, A_h, W_h, m0, n0, K, acc);

#pragma unroll
    for (int i = 0; i < 4; i++) {
        const int r0 = m0 + wr * 64 + i * 16 + (lane >> 2);
#pragma unroll
        for (int j = 0; j < 4; j++) {
            const int n = n0 + wc * 32 + j * 8 + 2 * (lane & 3);
            const float2 b2 = *(const float2*)&bias[n];
#pragma unroll
            for (int hf = 0; hf < 2; hf++) {
                const int m = r0 + hf * 8;
                float v0 = acc[i][j][hf * 2 + 0] + b2.x;
                float v1 = acc[i][j][hf * 2 + 1] + b2.y;
                if (EPI == EPI_RES) {
                    const size_t o = (size_t)m * N + n;
                    const float2 rr = *(const float2*)&res[o];
                    float2 w; w.x = v0 + rr.x; w.y = v1 + rr.y;
                    *(float2*)&Cf[o] = w;
                } else { // EPI_GELU -> fp16
                    const size_t o = (size_t)m * N + n;
                    *(uint32_t*)(Ch + o) = packh(gelu_exact(v0), gelu_exact(v1));
                }
            }
        }
    }
}

// --------------------------- flash attention (mma) --------------------------
// 128 q-rows/CTA, KV tile 64, 3-stage (wait_group 1), 2 CTAs/SM.
// smem: Q 16K | stage{K 8K, V 8K} x3 | mask 3x256B
#define ATT_Q   0
#define ATT_ST  16384
#define ATT_STG 16384
#define ATT_MSK (ATT_ST + 3*ATT_STG)
#define ATT_SMEM (ATT_MSK + 768 + 256)

__global__ void __launch_bounds__(256, 2) attn_mma(
    const fp16* __restrict__ qh, const fp16* __restrict__ kh,
    const fp16* __restrict__ vh,
    const float* __restrict__ mf,
    fp16* __restrict__ oh)
{
    extern __shared__ char smem[];
    const uint32_t sb = smem_u32(smem);
    const int tid = threadIdx.x;
    const int lane = tid & 31, wid = tid >> 5;
    const int b = blockIdx.z, h = blockIdx.y, q0 = blockIdx.x * 128;

    const size_t bh_off = ((size_t)(b * Hh + h) * Ss) * DH;
    const fp16* qhp = qh + bh_off + (size_t)q0 * DH;
    const fp16* khp = kh + bh_off;
    const fp16* vhp = vh + bh_off;
    const float* mfb = mf + b * Ss;

    auto load_kv = [&](int st, int kt) {
        const uint32_t s0 = sb + ATT_ST + st * ATT_STG;
        const int kv0 = kt * 64;
#pragma unroll
        for (int t = 0; t < 2; t++) {         // K,V: 64 rows x 128B each
            int idx = t * 256 + tid;          // 0..511
            int row = idx >> 3, c = idx & 7;
            uint32_t off = SWZ((uint32_t)(row * 128 + c * 16));
            size_t go = (size_t)(kv0 + row) * DH + c * 8;
            cp16(s0 + off,        khp + go);
            cp16(s0 + 8192 + off, vhp + go);
        }
        if (tid < 16) cp16(sb + ATT_MSK + st * 256 + tid * 16, mfb + kv0 + tid * 4);
    };

    {
#pragma unroll
        for (int t = 0; t < 4; t++) {         // Q: 128 rows x 128B
            int idx = t * 256 + tid;
            int row = idx >> 3, c = idx & 7;
            uint32_t off = SWZ((uint32_t)(row * 128 + c * 16));
            size_t go = (size_t)row * DH + c * 8;
            cp16(sb + ATT_Q + off, qhp + go);
        }
        load_kv(0, 0); CP_COMMIT();
        load_kv(1, 1); CP_COMMIT();
    }

    uint32_t qfh[4][4];
    float oacc[8][4];
#pragma unroll
    for (int q = 0; q < 8; q++)
#pragma unroll
        for (int e = 0; e < 4; e++) oacc[q][e] = 0.f;
    float mrow0 = -INFINITY, mrow1 = -INFINITY, lsum0 = 0.f, lsum1 = 0.f;

    const int lr16 = lane & 15;
    const int alc  = (lane >> 4) * 16;
    const int brow = (lane & 7) + ((lane >> 4) & 1) * 8;
    const int bcol = ((lane >> 3) & 1) * 16;
    const int vrow = (lane & 7) + ((lane >> 3) & 1) * 8;
    const int vcol = (lane >> 4) * 16;

    const int NKV = Ss / 64;      // 16 tiles
    int st = 0, stn = 2;
    for (int kt = 0; kt < NKV; kt++) {
        CP_WAIT1();               // stage kt (and Q on kt==0) complete
        __syncthreads();
        if (kt + 2 < NKV) load_kv(stn, kt + 2);
        CP_COMMIT();

        if (kt == 0) {
#pragma unroll
            for (int ks = 0; ks < 4; ks++) {
                uint32_t off = SWZ((uint32_t)((wid * 16 + lr16) * 128 + ks * 32 + alc));
                ldsm4(qfh[ks], sb + ATT_Q + off);
            }
        }

        const uint32_t sK = sb + ATT_ST + st * ATT_STG;
        const uint32_t sV = sK + 8192;
        const uint32_t sM = sb + ATT_MSK + st * 256;

        // ---- S = Q K^T  (16 q-rows x 64 kv-cols per warp) ----
        float sacc[8][4];
#pragma unroll
        for (int j = 0; j < 8; j++)
#pragma unroll
            for (int e = 0; e < 4; e++) sacc[j][e] = 0.f;

#pragma unroll
        for (int p = 0; p < 4; p++) {
#pragma unroll
            for (int ks = 0; ks < 4; ks++) {
                uint32_t koff = SWZ((uint32_t)((p * 16 + brow) * 128 + ks * 32 + bcol));
                uint32_t kbh[4];
                ldsm4(kbh, sK + koff);
#pragma unroll
                for (int a = 0; a < 2; a++)
                    mma_f16(sacc[p * 2 + a], qfh[ks], &kbh[2 * a]);
            }
        }

        // ---- online softmax over this 64-col tile ----
        float mx0 = -INFINITY, mx1 = -INFINITY;
#pragma unroll
        for (int j = 0; j < 8; j++) {
            mx0 = fmaxf(mx0, fmaxf(sacc[j][0], sacc[j][1]));
            mx1 = fmaxf(mx1, fmaxf(sacc[j][2], sacc[j][3]));
        }
        mx0 = fmaxf(mx0, __shfl_xor_sync(0xffffffffu, mx0, 1));
        mx0 = fmaxf(mx0, __shfl_xor_sync(0xffffffffu, mx0, 2));
        mx1 = fmaxf(mx1, __shfl_xor_sync(0xffffffffu, mx1, 1));
        mx1 = fmaxf(mx1, __shfl_xor_sync(0xffffffffu, mx1, 2));
        const float mnew0 = fmaxf(mrow0, mx0);
        const float mnew1 = fmaxf(mrow1, mx1);
        const float al0 = __expf(mrow0 - mnew0);
        const float al1 = __expf(mrow1 - mnew1);
        float ls0 = 0.f, ls1 = 0.f;
#pragma unroll
        for (int j = 0; j < 8; j++) {
            float2 mv;
            asm volatile("ld.shared.v2.f32 {%0,%1}, [%2];"
                : "=f"(mv.x), "=f"(mv.y)
                : "r"(sM + (uint32_t)((j * 8 + 2 * (lane & 3)) * 4)));
            float p0 = __expf(sacc[j][0] - mnew0) * mv.x;
            float p1 = __expf(sacc[j][1] - mnew0) * mv.y;
            float p2 = __expf(sacc[j][2] - mnew1) * mv.x;
            float p3 = __expf(sacc[j][3] - mnew1) * mv.y;
            sacc[j][0] = p0; sacc[j][1] = p1; sacc[j][2] = p2; sacc[j][3] = p3;
            ls0 += p0 + p1; ls1 += p2 + p3;
        }
        ls0 += __shfl_xor_sync(0xffffffffu, ls0, 1);
        ls0 += __shfl_xor_sync(0xffffffffu, ls0, 2);
        ls1 += __shfl_xor_sync(0xffffffffu, ls1, 1);
        ls1 += __shfl_xor_sync(0xffffffffu, ls1, 2);
        lsum0 = lsum0 * al0 + ls0;
        lsum1 = lsum1 * al1 + ls1;
        mrow0 = mnew0; mrow1 = mnew1;
#pragma unroll
        for (int q = 0; q < 8; q++) {
            oacc[q][0] *= al0; oacc[q][1] *= al0;
            oacc[q][2] *= al1; oacc[q][3] *= al1;
        }

        // ---- O += P * V  (P truncated to fp16) ----
#pragma unroll
        for (int ks = 0; ks < 4; ks++) {
            uint32_t ph[4];
            {
                const float* s0 = sacc[2 * ks];
                const float* s1 = sacc[2 * ks + 1];
                ph[0] = packh(s0[0], s0[1]); ph[1] = packh(s0[2], s0[3]);
                ph[2] = packh(s1[0], s1[1]); ph[3] = packh(s1[2], s1[3]);
            }
#pragma unroll
            for (int q = 0; q < 4; q++) {
                uint32_t voff = SWZ((uint32_t)((ks * 16 + vrow) * 128 + q * 32 + vcol));
                uint32_t vbh[4];
                ldsm4t(vbh, sV + voff);
#pragma unroll
                for (int a = 0; a < 2; a++)
                    mma_f16(oacc[q * 2 + a], ph, &vbh[2 * a]);
            }
        }
        st  = (st  == 2) ? 0 : st + 1;
        stn = (stn == 2) ? 0 : stn + 1;
    }

    const float inv0 = 1.f / lsum0;
    const float inv1 = 1.f / lsum1;
    const int tok0 = b * Ss + q0 + wid * 16 + (lane >> 2);
#pragma unroll
    for (int q = 0; q < 8; q++) {
        const int col = h * DH + q * 8 + 2 * (lane & 3);
        *(uint32_t*)(oh + (size_t)tok0 * Dd + col) =
            packh(oacc[q][0] * inv0, oacc[q][1] * inv0);
        *(uint32_t*)(oh + (size_t)(tok0 + 8) * Dd + col) =
            packh(oacc[q][2] * inv1, oacc[q][3] * inv1);
    }
}

// ------------------------------ LayerNorm -----------------------------------
template<bool WB>
__global__ void __launch_bounds__(256) ln_k(
    const float* __restrict__ X, const float* __restrict__ gg,
    const float* __restrict__ bb, float* __restrict__ Y,
    fp16* __restrict__ Yh)
{
    __shared__ float red[16];
    const int row = blockIdx.x, tid = threadIdx.x;
    const float4 x = ((const float4*)(X + (size_t)row * Dd))[tid];
    float s  = x.x + x.y + x.z + x.w;
    float s2 = x.x*x.x + x.y*x.y + x.z*x.z + x.w*x.w;
#pragma unroll
    for (int o = 16; o; o >>= 1) {
        s  += __shfl_xor_sync(0xffffffffu, s,  o);
        s2 += __shfl_xor_sync(0xffffffffu, s2, o);
    }
    const int w = tid >> 5, lane = tid & 31;
    if (lane == 0) { red[w] = s; red[8 + w] = s2; }
    __syncthreads();
    if (tid < 32) {
        float a = (tid < 8) ? red[tid]     : 0.f;
        float c = (tid < 8) ? red[8 + tid] : 0.f;
#pragma unroll
        for (int o = 4; o; o >>= 1) {
            a += __shfl_xor_sync(0xffffffffu, a, o);
            c += __shfl_xor_sync(0xffffffffu, c, o);
        }
        if (tid == 0) { red[0] = a; red[8] = c; }
    }
    __syncthreads();
    const float mean = red[0] * (1.f / Dd);
    const float var  = red[8] * (1.f / Dd) - mean * mean;
    const float rstd = rsqrtf(var + 1e-12f);
    const float4 gv = ((const float4*)gg)[tid];
    const float4 bv = ((const float4*)bb)[tid];
    float4 y;
    y.x = (x.x - mean) * rstd * gv.x + bv.x;
    y.y = (x.y - mean) * rstd * gv.y + bv.y;
    y.z = (x.z - mean) * rstd * gv.z + bv.z;
    y.w = (x.w - mean) * rstd * gv.w + bv.w;
    ((float4*)(Y + (size_t)row * Dd))[tid] = y;
    if (WB) {
        uint2 vh2;
        vh2.x = packh(y.x, y.y);  vh2.y = packh(y.z, y.w);
        ((uint2*)(Yh + (size_t)row * Dd))[tid] = vh2;
    }
}

// -------------------------- fp32 -> fp16 conversions ------------------------
__global__ void __launch_bounds__(256) cvth_k(
    const float* __restrict__ X, fp16* __restrict__ Hc, int n4)
{
    int i = blockIdx.x * 256 + threadIdx.x;
    if (i >= n4) return;
    float4 v = ((const float4*)X)[i];
    uint2 vh2;
    vh2.x = packh(v.x, v.y);  vh2.y = packh(v.z, v.w);
    ((uint2*)Hc)[i] = vh2;
}

// two equal-size arrays in one launch (W1, W2)
__global__ void __launch_bounds__(256) cvt2h_k(
    const float* __restrict__ X0, fp16* __restrict__ H0,
    const float* __restrict__ X1, fp16* __restrict__ H1, int n4)
{
    const float* X = blockIdx.y ? X1 : X0;
    fp16* Hc = blockIdx.y ? H1 : H0;
    int i = blockIdx.x * 256 + threadIdx.x;
    if (i >= n4) return;
    float4 v = ((const float4*)X)[i];
    uint2 vh2;
    vh2.x = packh(v.x, v.y);  vh2.y = packh(v.z, v.w);
    ((uint2*)Hc)[i] = vh2;
}

__global__ void __launch_bounds__(256) cvt4h_k(int n4)
{
    const int a = blockIdx.y;
    int i = blockIdx.x * 256 + threadIdx.x;
    if (i >= n4) return;
    const float* X = g_cvt_src[a];
    fp16* Hc = g_cvt_dh[a];
    float4 v = ((const float4*)X)[i];
    uint2 vh2;
    vh2.x = packh(v.x, v.y);  vh2.y = packh(v.z, v.w);
    ((uint2*)Hc)[i] = vh2;
}

__global__ void __launch_bounds__(256) maskf_k(const int* __restrict__ m,
                                              float* __restrict__ mfo, int n)
{
    int i = blockIdx.x * 256 + threadIdx.x;
    if (i < n) mfo[i] = (m[i] != 0) ? 1.f : 0.f;
}

// ------------------------------ launch --------------------------------------
extern "C" void kernel_launch(void* const* d_in, const int* in_sizes, int n_in,
                              void* d_out, int out_size)
{
    const float* x    = (const float*)d_in[0];
    const int*   amsk = (const int*)  d_in[1];
    const float* Wq   = (const float*)d_in[2];
    const float* bq   = (const float*)d_in[3];
    const float* Wk   = (const float*)d_in[4];
    const float* bk   = (const float*)d_in[5];
    const float* Wv   = (const float*)d_in[6];
    const float* bv   = (const float*)d_in[7];
    const float* Wo   = (const float*)d_in[8];
    const float* bo   = (const float*)d_in[9];
    const float* ln1g = (const float*)d_in[10];
    const float* ln1b = (const float*)d_in[11];
    const float* W1   = (const float*)d_in[12];
    const float* b1   = (const float*)d_in[13];
    const float* W2   = (const float*)d_in[14];
    const float* b2   = (const float*)d_in[15];
    const float* ln2g = (const float*)d_in[16];
    const float* ln2b = (const float*)d_in[17];
    float* out = (float*)d_out;

    float *sap, *hp, *f2p, *mfp;
    fp16 *xh, *qhp, *khp, *vhp, *cxh, *hhp, *fhp;
    fp16 *wqh, *wkh, *wvh, *woh, *w1h, *w2h;
    cudaGetSymbolAddress((void**)&sap, g_sa);  cudaGetSymbolAddress((void**)&hp,  g_h);
    cudaGetSymbolAddress((void**)&f2p, g_f2);  cudaGetSymbolAddress((void**)&mfp, g_mf);
    cudaGetSymbolAddress((void**)&xh,  g_xh);
    cudaGetSymbolAddress((void**)&qhp, g_qh);
    cudaGetSymbolAddress((void**)&khp, g_kh);  cudaGetSymbolAddress((void**)&vhp, g_vh);
    cudaGetSymbolAddress((void**)&cxh, g_cxh);
    cudaGetSymbolAddress((void**)&hhp, g_hh);
    cudaGetSymbolAddress((void**)&fhp, g_fh);
    cudaGetSymbolAddress((void**)&wqh, g_wqh); cudaGetSymbolAddress((void**)&wkh, g_wkh);
    cudaGetSymbolAddress((void**)&wvh, g_wvh); cudaGetSymbolAddress((void**)&woh, g_woh);
    cudaGetSymbolAddress((void**)&w1h, g_w1h); cudaGetSymbolAddress((void**)&w2h, g_w2h);

    static const float* h_src[4];
    static fp16* h_dh[4];
    h_src[0] = Wq; h_src[1] = Wk; h_src[2] = Wv; h_src[3] = Wo;
    h_dh[0] = wqh; h_dh[1] = wkh; h_dh[2] = wvh; h_dh[3] = woh;
    void *d_src_tab, *d_dh_tab;
    cudaGetSymbolAddress(&d_src_tab, g_cvt_src);
    cudaGetSymbolAddress(&d_dh_tab,  g_cvt_dh);
    cudaMemcpyAsync(d_src_tab, h_src, sizeof(h_src), cudaMemcpyHostToDevice);
    cudaMemcpyAsync(d_dh_tab,  h_dh,  sizeof(h_dh),  cudaMemcpyHostToDevice);

    cudaFuncSetAttribute(gemm_qkv,           cudaFuncAttributeMaxDynamicSharedMemorySize, GEMM_SMEM);
    cudaFuncSetAttribute(gemm_mma<EPI_RES>,  cudaFuncAttributeMaxDynamicSharedMemorySize, GEMM_SMEM);
    cudaFuncSetAttribute(gemm_mma<EPI_GELU>, cudaFuncAttributeMaxDynamicSharedMemorySize, GEMM_SMEM);
    cudaFuncSetAttribute(attn_mma, cudaFuncAttributeMaxDynamicSharedMemorySize, ATT_SMEM);

    dim3 gD(Dd/128, TT/128);    // (8, 64)
    dim3 gF(Ff/128, TT/128);    // (32, 64)

    // Launches: 1 cvt_x, 2 cvt4h(weights), 3 maskf, 4 qkv, 5 attn, 6 O-gemm.
    cvth_k<<<(TT*Dd/4 + 255)/256, 256>>>(x, xh, TT*Dd/4);                       // 1
    cvt4h_k<<<dim3((Dd*Dd/4 + 255)/256, 4), 256>>>(Dd*Dd/4);                    // 2
    maskf_k<<<(Bb*Ss + 255)/256, 256>>>(amsk, mfp, Bb*Ss);                      // 3

    // 4. fused QKV projection
    gemm_qkv<<<dim3(24, TT/128), 256, GEMM_SMEM>>>(xh, wqh, wkh, wvh,
                                                   bq, bk, bv, qhp, khp, vhp);

    // 5. attention -> ctx fp16
    attn_mma<<<dim3(Ss/128, Hh, Bb), 256, ATT_SMEM>>>(qhp, khp, vhp, mfp, cxh);

    // 6. output projection + residual (fp32)
    gemm_mma<EPI_RES><<<gD, 256, GEMM_SMEM>>>(cxh, woh, bo, x,
                                              sap, nullptr, Dd, Dd);

    // 7. LN1 -> fp32 + fp16
    ln_k<true><<<TT, 256>>>(sap, ln1g, ln1b, hp, hhp);

    // 8. cvt W1 + W2 in one launch
    cvt2h_k<<<dim3((Ff*Dd/4 + 255)/256, 2), 256>>>(W1, w1h, W2, w2h, Ff*Dd/4);

    // 9. FFN up + gelu -> fp16
    gemm_mma<EPI_GELU><<<gF, 256, GEMM_SMEM>>>(hhp, w1h, b1, nullptr,
                                               nullptr, fhp, Ff, Dd);

    // 10. FFN down + residual (fp32)
    gemm_mma<EPI_RES><<<gD, 256, GEMM_SMEM>>>(fhp, w2h, b2, hp,
                                              f2p, nullptr, Dd, Ff);

    // 11. LN2 -> output
    ln_k<false><<<TT, 256>>>(f2p, ln2g, ln2b, out, nullptr);
}